// round 3
// baseline (speedup 1.0000x reference)
#include <cuda_runtime.h>
#include <cstdint>

// ---------------- problem constants ----------------
#define NNODES   100000
#define DIN      512
#define DOUT     256
#define KEEP_THRESH 7549747u          // 0.9f == 7549747 * 2^-23 exactly
#define INV_KEEP (1.0f/0.9f)

// scratch: h = dropout(x) @ W   [NNODES, DOUT] fp32 (102.4 MB)
__device__ float g_h[(size_t)NNODES * DOUT];

// ---------------- JAX threefry2x32, PARTITIONABLE layout (key = (0,42)) ----
// element i: (o0,o1) = threefry2x32(key, (hi64(i), lo64(i))) = (0, i);
// 32-bit random bits = o0 ^ o1.
__device__ __forceinline__ uint32_t rotl32(uint32_t x, int r) {
    return __funnelshift_l(x, x, r);
}

__device__ __forceinline__ uint32_t threefry_bits(uint32_t idx) {
    const uint32_t ks0 = 0u;
    const uint32_t ks1 = 42u;
    const uint32_t ks2 = 0x1BD11BDAu ^ 42u;
    uint32_t x0 = 0u;          // counter hi word (size < 2^32)
    uint32_t x1 = idx;         // counter lo word
    x0 += ks0; x1 += ks1;
#define TFR(r) { x0 += x1; x1 = rotl32(x1, r); x1 ^= x0; }
    TFR(13) TFR(15) TFR(26) TFR(6)   x0 += ks1; x1 += ks2 + 1u;
    TFR(17) TFR(29) TFR(16) TFR(24)  x0 += ks2; x1 += ks0 + 2u;
    TFR(13) TFR(15) TFR(26) TFR(6)   x0 += ks0; x1 += ks1 + 3u;
    TFR(17) TFR(29) TFR(16) TFR(24)  x0 += ks1; x1 += ks2 + 4u;
    TFR(13) TFR(15) TFR(26) TFR(6)   x0 += ks2; x1 += ks0 + 5u;
#undef TFR
    return x0 ^ x1;            // partitionable 32-bit combine
}

__device__ __forceinline__ float dropout_val(float v, uint32_t idx) {
    uint32_t m = threefry_bits(idx) >> 9;
    return (m < KEEP_THRESH) ? v * INV_KEEP : 0.0f;
}

// ---------------- kernel 1: fused dropout + GEMM (fp32) ----------------
// h[M, 256] = dropout(x)[M,512] @ W[512,256]
// tiles: BM=64, BN=128, BK=16 ; 256 threads (16x16), 4x8 per thread
#define BM 64
#define BN 128
#define BK 16
#define TM 4
#define TN 8

__global__ __launch_bounds__(256) void gemm_dropout_kernel(
    const float* __restrict__ x, const float* __restrict__ W, int M)
{
    __shared__ float As[BK][BM + 4];   // [k][m], padded
    __shared__ float Bs[BK][BN + 4];   // [k][n], padded

    const int bn = blockIdx.x * BN;
    const int bm = blockIdx.y * BM;
    const int tx = threadIdx.x;        // 0..15 -> N
    const int ty = threadIdx.y;        // 0..15 -> M
    const int tid = ty * 16 + tx;

    const int lrow = tid >> 2;             // 0..63
    const int lcol = (tid & 3) * 4;        // 0,4,8,12
    const int wrow = tid >> 5;             // 0..7
    const int wcol = (tid & 31) * 4;       // 0..124

    float acc[TM][TN];
#pragma unroll
    for (int i = 0; i < TM; ++i)
#pragma unroll
        for (int j = 0; j < TN; ++j) acc[i][j] = 0.0f;

    const int grow = bm + lrow;
    const bool rok = (grow < M);

    for (int k0 = 0; k0 < DIN; k0 += BK) {
        // load + dropout x tile
        float4 v = make_float4(0.f, 0.f, 0.f, 0.f);
        if (rok) {
            v = *(const float4*)(x + (size_t)grow * DIN + k0 + lcol);
            uint32_t base = (uint32_t)grow * DIN + (uint32_t)(k0 + lcol);
            v.x = dropout_val(v.x, base);
            v.y = dropout_val(v.y, base + 1u);
            v.z = dropout_val(v.z, base + 2u);
            v.w = dropout_val(v.w, base + 3u);
        }
        As[lcol + 0][lrow] = v.x;
        As[lcol + 1][lrow] = v.y;
        As[lcol + 2][lrow] = v.z;
        As[lcol + 3][lrow] = v.w;

        // load W tile
#pragma unroll
        for (int i = 0; i < 2; ++i) {
            int r = wrow + i * 8;
            float4 wv = *(const float4*)(W + (size_t)(k0 + r) * DOUT + bn + wcol);
            *(float4*)&Bs[r][wcol] = wv;
        }
        __syncthreads();

#pragma unroll
        for (int k = 0; k < BK; ++k) {
            float4 a  = *(const float4*)&As[k][ty * TM];
            float4 b0 = *(const float4*)&Bs[k][tx * TN];
            float4 b1 = *(const float4*)&Bs[k][tx * TN + 4];
            float am[TM] = {a.x, a.y, a.z, a.w};
            float bn_[TN] = {b0.x, b0.y, b0.z, b0.w, b1.x, b1.y, b1.z, b1.w};
#pragma unroll
            for (int i = 0; i < TM; ++i)
#pragma unroll
                for (int j = 0; j < TN; ++j)
                    acc[i][j] += am[i] * bn_[j];
        }
        __syncthreads();
    }

    // write h
#pragma unroll
    for (int i = 0; i < TM; ++i) {
        int row = bm + ty * TM + i;
        if (row < M) {
            float* hp = g_h + (size_t)row * DOUT + bn + tx * TN;
            *(float4*)(hp)     = make_float4(acc[i][0], acc[i][1], acc[i][2], acc[i][3]);
            *(float4*)(hp + 4) = make_float4(acc[i][4], acc[i][5], acc[i][6], acc[i][7]);
        }
    }
}

// ---------------- kernel 2: zero output ----------------
__global__ void zero_kernel(float4* out, int n4) {
    int i = blockIdx.x * blockDim.x + threadIdx.x;
    if (i < n4) out[i] = make_float4(0.f, 0.f, 0.f, 0.f);
}

// ---------------- kernel 3: edge scatter with vector reductions ----------------
__device__ __forceinline__ void red_add_v4(float4* addr, float4 v) {
    asm volatile("red.global.add.v4.f32 [%0], {%1, %2, %3, %4};"
                 :: "l"(addr), "f"(v.x), "f"(v.y), "f"(v.z), "f"(v.w)
                 : "memory");
}

__global__ __launch_bounds__(256) void scatter_kernel(
    const int* __restrict__ esrc, const int* __restrict__ edst,
    const float* __restrict__ ew, float* __restrict__ out, int E)
{
    int warp = (blockIdx.x * blockDim.x + threadIdx.x) >> 5;
    int lane = threadIdx.x & 31;
    if (warp >= E) return;

    int s   = esrc[warp];
    int d   = edst[warp];
    float w = ew[warp];

    const float4* hp = (const float4*)(g_h + (size_t)s * DOUT);  // 64 float4
    float4*       op = (float4*)(out + (size_t)d * DOUT);

    float4 v0 = hp[lane];
    float4 v1 = hp[lane + 32];
    v0.x *= w; v0.y *= w; v0.z *= w; v0.w *= w;
    v1.x *= w; v1.y *= w; v1.z *= w; v1.w *= w;
    red_add_v4(op + lane,      v0);
    red_add_v4(op + lane + 32, v1);
}

// ---------------- kernel 4: relu ----------------
__global__ void relu_kernel(float4* out, int n4) {
    int i = blockIdx.x * blockDim.x + threadIdx.x;
    if (i < n4) {
        float4 v = out[i];
        v.x = fmaxf(v.x, 0.f); v.y = fmaxf(v.y, 0.f);
        v.z = fmaxf(v.z, 0.f); v.w = fmaxf(v.w, 0.f);
        out[i] = v;
    }
}

// ---------------- launch ----------------
extern "C" void kernel_launch(void* const* d_in, const int* in_sizes, int n_in,
                              void* d_out, int out_size)
{
    const float* x    = (const float*)d_in[0];
    const float* W    = (const float*)d_in[1];
    const int*   esrc = (const int*)d_in[2];
    const int*   edst = (const int*)d_in[3];
    const float* ew   = (const float*)d_in[4];
    float*       out  = (float*)d_out;

    const int M = in_sizes[0] / DIN;   // 100000
    const int E = in_sizes[2];         // 3200000

    // 1) h = dropout(x) @ W
    dim3 gblk(DOUT / BN, (M + BM - 1) / BM);
    gemm_dropout_kernel<<<gblk, dim3(16, 16)>>>(x, W, M);

    // 2) out = 0
    int n4 = out_size / 4;
    zero_kernel<<<(n4 + 255) / 256, 256>>>((float4*)out, n4);

    // 3) scatter-add edges (1 warp per edge)
    int blocks = (E + 7) / 8;          // 8 warps / block
    scatter_kernel<<<blocks, 256>>>(esrc, edst, ew, out, E);

    // 4) relu
    relu_kernel<<<(n4 + 255) / 256, 256>>>((float4*)out, n4);
}

// round 4
// speedup vs baseline: 1.3074x; 1.3074x over previous
#include <cuda_runtime.h>
#include <cstdint>

// ---------------- problem constants ----------------
#define NNODES   100000
#define DIN      512
#define DOUT     256
#define EDGES_MAX 3200000
#define KEEP_THRESH 7549747u          // 0.9f == 7549747 * 2^-23 exactly
#define INV_KEEP (1.0f/0.9f)

// scratch
__device__ float g_h[(size_t)NNODES * DOUT];     // h = dropout(x) @ W  (102.4 MB)
__device__ int   g_count[NNODES];                // per-dst degree
__device__ int   g_off[NNODES + 1];              // CSR offsets
__device__ int   g_cursor[NNODES];               // write cursors
__device__ int2  g_edge_s[EDGES_MAX];            // (src, w-bits) sorted by dst

// ---------------- JAX threefry2x32, partitionable layout (key = (0,42)) ----
__device__ __forceinline__ uint32_t rotl32(uint32_t x, int r) {
    return __funnelshift_l(x, x, r);
}

__device__ __forceinline__ uint32_t threefry_bits(uint32_t idx) {
    const uint32_t ks0 = 0u;
    const uint32_t ks1 = 42u;
    const uint32_t ks2 = 0x1BD11BDAu ^ 42u;
    uint32_t x0 = 0u;          // counter hi word
    uint32_t x1 = idx;         // counter lo word
    x0 += ks0; x1 += ks1;
#define TFR(r) { x0 += x1; x1 = rotl32(x1, r); x1 ^= x0; }
    TFR(13) TFR(15) TFR(26) TFR(6)   x0 += ks1; x1 += ks2 + 1u;
    TFR(17) TFR(29) TFR(16) TFR(24)  x0 += ks2; x1 += ks0 + 2u;
    TFR(13) TFR(15) TFR(26) TFR(6)   x0 += ks0; x1 += ks1 + 3u;
    TFR(17) TFR(29) TFR(16) TFR(24)  x0 += ks1; x1 += ks2 + 4u;
    TFR(13) TFR(15) TFR(26) TFR(6)   x0 += ks2; x1 += ks0 + 5u;
#undef TFR
    return x0 ^ x1;            // partitionable 32-bit combine
}

__device__ __forceinline__ float dropout_val(float v, uint32_t idx) {
    uint32_t m = threefry_bits(idx) >> 9;
    return (m < KEEP_THRESH) ? v * INV_KEEP : 0.0f;
}

// ---------------- kernel 1: fused dropout + GEMM (fp32) ----------------
#define BM 64
#define BN 128
#define BK 16
#define TM 4
#define TN 8

__global__ __launch_bounds__(256) void gemm_dropout_kernel(
    const float* __restrict__ x, const float* __restrict__ W, int M)
{
    __shared__ float As[BK][BM + 4];
    __shared__ float Bs[BK][BN + 4];

    const int bn = blockIdx.x * BN;
    const int bm = blockIdx.y * BM;
    const int tx = threadIdx.x;
    const int ty = threadIdx.y;
    const int tid = ty * 16 + tx;

    const int lrow = tid >> 2;
    const int lcol = (tid & 3) * 4;
    const int wrow = tid >> 5;
    const int wcol = (tid & 31) * 4;

    float acc[TM][TN];
#pragma unroll
    for (int i = 0; i < TM; ++i)
#pragma unroll
        for (int j = 0; j < TN; ++j) acc[i][j] = 0.0f;

    const int grow = bm + lrow;
    const bool rok = (grow < M);

    for (int k0 = 0; k0 < DIN; k0 += BK) {
        float4 v = make_float4(0.f, 0.f, 0.f, 0.f);
        if (rok) {
            v = *(const float4*)(x + (size_t)grow * DIN + k0 + lcol);
            uint32_t base = (uint32_t)grow * DIN + (uint32_t)(k0 + lcol);
            v.x = dropout_val(v.x, base);
            v.y = dropout_val(v.y, base + 1u);
            v.z = dropout_val(v.z, base + 2u);
            v.w = dropout_val(v.w, base + 3u);
        }
        As[lcol + 0][lrow] = v.x;
        As[lcol + 1][lrow] = v.y;
        As[lcol + 2][lrow] = v.z;
        As[lcol + 3][lrow] = v.w;

#pragma unroll
        for (int i = 0; i < 2; ++i) {
            int r = wrow + i * 8;
            float4 wv = *(const float4*)(W + (size_t)(k0 + r) * DOUT + bn + wcol);
            *(float4*)&Bs[r][wcol] = wv;
        }
        __syncthreads();

#pragma unroll
        for (int k = 0; k < BK; ++k) {
            float4 a  = *(const float4*)&As[k][ty * TM];
            float4 b0 = *(const float4*)&Bs[k][tx * TN];
            float4 b1 = *(const float4*)&Bs[k][tx * TN + 4];
            float am[TM] = {a.x, a.y, a.z, a.w};
            float bn_[TN] = {b0.x, b0.y, b0.z, b0.w, b1.x, b1.y, b1.z, b1.w};
#pragma unroll
            for (int i = 0; i < TM; ++i)
#pragma unroll
                for (int j = 0; j < TN; ++j)
                    acc[i][j] += am[i] * bn_[j];
        }
        __syncthreads();
    }

#pragma unroll
    for (int i = 0; i < TM; ++i) {
        int row = bm + ty * TM + i;
        if (row < M) {
            float* hp = g_h + (size_t)row * DOUT + bn + tx * TN;
            *(float4*)(hp)     = make_float4(acc[i][0], acc[i][1], acc[i][2], acc[i][3]);
            *(float4*)(hp + 4) = make_float4(acc[i][4], acc[i][5], acc[i][6], acc[i][7]);
        }
    }
}

// ---------------- CSR build ----------------
__global__ void zero_count_kernel() {
    int i = blockIdx.x * blockDim.x + threadIdx.x;
    if (i < NNODES) g_count[i] = 0;
}

__global__ void hist_kernel(const int* __restrict__ edst, int E) {
    int e = blockIdx.x * blockDim.x + threadIdx.x;
    if (e < E) atomicAdd(&g_count[edst[e]], 1);
}

// single-block Hillis-Steele scan over NNODES counts -> offsets + cursors
__global__ __launch_bounds__(1024) void scan_kernel() {
    __shared__ int sh[1024];
    const int tid = threadIdx.x;
    int total = 0;
    for (int base = 0; base < NNODES; base += 1024) {
        int i = base + tid;
        int v = (i < NNODES) ? g_count[i] : 0;
        sh[tid] = v;
        __syncthreads();
#pragma unroll
        for (int off = 1; off < 1024; off <<= 1) {
            int y = (tid >= off) ? sh[tid - off] : 0;
            __syncthreads();
            sh[tid] += y;
            __syncthreads();
        }
        int excl = sh[tid] - v;
        if (i < NNODES) {
            g_off[i]    = total + excl;
            g_cursor[i] = total + excl;
        }
        int bsum = sh[1023];
        __syncthreads();
        total += bsum;
    }
    if (tid == 0) g_off[NNODES] = total;
}

__global__ void reorder_kernel(const int* __restrict__ esrc,
                               const int* __restrict__ edst,
                               const float* __restrict__ ew, int E)
{
    int e = blockIdx.x * blockDim.x + threadIdx.x;
    if (e < E) {
        int d = edst[e];
        int pos = atomicAdd(&g_cursor[d], 1);
        g_edge_s[pos] = make_int2(esrc[e], __float_as_int(ew[e]));
    }
}

// ---------------- aggregation: 1 warp per dst node, no atomics ----------------
__global__ __launch_bounds__(256) void agg_kernel(float* __restrict__ out, int N)
{
    int node = blockIdx.x * 8 + (threadIdx.x >> 5);
    int lane = threadIdx.x & 31;
    if (node >= N) return;

    int beg = g_off[node];
    int end = g_off[node + 1];

    float4 a0 = make_float4(0.f, 0.f, 0.f, 0.f);
    float4 a1 = make_float4(0.f, 0.f, 0.f, 0.f);

    for (int j = beg; j < end; j += 32) {
        int n = min(32, end - j);
        int2 e = (lane < n) ? __ldg(&g_edge_s[j + lane]) : make_int2(0, 0);
        for (int t = 0; t < n; ++t) {
            int   s = __shfl_sync(0xffffffffu, e.x, t);
            float w = __int_as_float(__shfl_sync(0xffffffffu, e.y, t));
            const float4* hp = (const float4*)(g_h + (size_t)s * DOUT);
            float4 v0 = __ldg(hp + lane);
            float4 v1 = __ldg(hp + lane + 32);
            a0.x = fmaf(w, v0.x, a0.x); a0.y = fmaf(w, v0.y, a0.y);
            a0.z = fmaf(w, v0.z, a0.z); a0.w = fmaf(w, v0.w, a0.w);
            a1.x = fmaf(w, v1.x, a1.x); a1.y = fmaf(w, v1.y, a1.y);
            a1.z = fmaf(w, v1.z, a1.z); a1.w = fmaf(w, v1.w, a1.w);
        }
    }

    a0.x = fmaxf(a0.x, 0.f); a0.y = fmaxf(a0.y, 0.f);
    a0.z = fmaxf(a0.z, 0.f); a0.w = fmaxf(a0.w, 0.f);
    a1.x = fmaxf(a1.x, 0.f); a1.y = fmaxf(a1.y, 0.f);
    a1.z = fmaxf(a1.z, 0.f); a1.w = fmaxf(a1.w, 0.f);

    float4* op = (float4*)(out + (size_t)node * DOUT);
    op[lane]      = a0;
    op[lane + 32] = a1;
}

// ---------------- launch ----------------
extern "C" void kernel_launch(void* const* d_in, const int* in_sizes, int n_in,
                              void* d_out, int out_size)
{
    const float* x    = (const float*)d_in[0];
    const float* W    = (const float*)d_in[1];
    const int*   esrc = (const int*)d_in[2];
    const int*   edst = (const int*)d_in[3];
    const float* ew   = (const float*)d_in[4];
    float*       out  = (float*)d_out;

    const int M = in_sizes[0] / DIN;   // 100000
    const int E = in_sizes[2];         // 3200000

    // 1) h = dropout(x) @ W
    dim3 gblk(DOUT / BN, (M + BM - 1) / BM);
    gemm_dropout_kernel<<<gblk, dim3(16, 16)>>>(x, W, M);

    // 2) CSR build (dst-major edge ordering)
    zero_count_kernel<<<(NNODES + 255) / 256, 256>>>();
    hist_kernel<<<(E + 255) / 256, 256>>>(edst, E);
    scan_kernel<<<1, 1024>>>();
    reorder_kernel<<<(E + 255) / 256, 256>>>(esrc, edst, ew, E);

    // 3) aggregate + relu, one warp per dst node, plain stores
    agg_kernel<<<(M + 7) / 8, 256>>>(out, M);
}

// round 5
// speedup vs baseline: 1.5971x; 1.2216x over previous
#include <cuda_runtime.h>
#include <cuda_fp16.h>
#include <cstdint>

// ---------------- problem constants ----------------
#define NNODES   100000
#define DIN      512
#define DOUT     256
#define EDGES_MAX 3200000
#define KEEP_THRESH 7549747u          // 0.9f == 7549747 * 2^-23 exactly
#define INV_KEEP (1.0f/0.9f)
#define SCAN_BLK  98                  // ceil(100000/1024)

// scratch
__device__ __half g_h[(size_t)NNODES * DOUT];    // h = dropout(x) @ W  (51.2 MB, fp16)
__device__ int    g_count[NNODES];               // per-dst degree
__device__ int    g_off[NNODES + 1];             // CSR offsets
__device__ int    g_cursor[NNODES];              // write cursors
__device__ int    g_bsum[SCAN_BLK];              // scan partials
__device__ int    g_bpre[SCAN_BLK];              // scan block prefixes
__device__ int2   g_edge_s[EDGES_MAX];           // (src, w-bits) sorted by dst

// ---------------- JAX threefry2x32, partitionable layout (key = (0,42)) ----
__device__ __forceinline__ uint32_t rotl32(uint32_t x, int r) {
    return __funnelshift_l(x, x, r);
}

__device__ __forceinline__ uint32_t threefry_bits(uint32_t idx) {
    const uint32_t ks0 = 0u;
    const uint32_t ks1 = 42u;
    const uint32_t ks2 = 0x1BD11BDAu ^ 42u;
    uint32_t x0 = 0u;
    uint32_t x1 = idx;
    x0 += ks0; x1 += ks1;
#define TFR(r) { x0 += x1; x1 = rotl32(x1, r); x1 ^= x0; }
    TFR(13) TFR(15) TFR(26) TFR(6)   x0 += ks1; x1 += ks2 + 1u;
    TFR(17) TFR(29) TFR(16) TFR(24)  x0 += ks2; x1 += ks0 + 2u;
    TFR(13) TFR(15) TFR(26) TFR(6)   x0 += ks0; x1 += ks1 + 3u;
    TFR(17) TFR(29) TFR(16) TFR(24)  x0 += ks1; x1 += ks2 + 4u;
    TFR(13) TFR(15) TFR(26) TFR(6)   x0 += ks2; x1 += ks0 + 5u;
#undef TFR
    return x0 ^ x1;
}

__device__ __forceinline__ float dropout_val(float v, uint32_t idx) {
    uint32_t m = threefry_bits(idx) >> 9;
    return (m < KEEP_THRESH) ? v * INV_KEEP : 0.0f;
}

// ---------------- kernel 1: fused dropout + GEMM (fp32, fp16 h store) ------
#define BM 64
#define BN 128
#define BK 16
#define TM 4
#define TN 8

__global__ __launch_bounds__(256) void gemm_dropout_kernel(
    const float* __restrict__ x, const float* __restrict__ W, int M)
{
    __shared__ float As[BK][BM + 4];
    __shared__ float Bs[BK][BN + 4];

    const int bn = blockIdx.x * BN;
    const int bm = blockIdx.y * BM;
    const int tx = threadIdx.x;
    const int ty = threadIdx.y;
    const int tid = ty * 16 + tx;

    const int lrow = tid >> 2;
    const int lcol = (tid & 3) * 4;
    const int wrow = tid >> 5;
    const int wcol = (tid & 31) * 4;

    float acc[TM][TN];
#pragma unroll
    for (int i = 0; i < TM; ++i)
#pragma unroll
        for (int j = 0; j < TN; ++j) acc[i][j] = 0.0f;

    const int grow = bm + lrow;
    const bool rok = (grow < M);

    for (int k0 = 0; k0 < DIN; k0 += BK) {
        float4 v = make_float4(0.f, 0.f, 0.f, 0.f);
        if (rok) {
            v = *(const float4*)(x + (size_t)grow * DIN + k0 + lcol);
            uint32_t base = (uint32_t)grow * DIN + (uint32_t)(k0 + lcol);
            v.x = dropout_val(v.x, base);
            v.y = dropout_val(v.y, base + 1u);
            v.z = dropout_val(v.z, base + 2u);
            v.w = dropout_val(v.w, base + 3u);
        }
        As[lcol + 0][lrow] = v.x;
        As[lcol + 1][lrow] = v.y;
        As[lcol + 2][lrow] = v.z;
        As[lcol + 3][lrow] = v.w;

#pragma unroll
        for (int i = 0; i < 2; ++i) {
            int r = wrow + i * 8;
            float4 wv = *(const float4*)(W + (size_t)(k0 + r) * DOUT + bn + wcol);
            *(float4*)&Bs[r][wcol] = wv;
        }
        __syncthreads();

#pragma unroll
        for (int k = 0; k < BK; ++k) {
            float4 a  = *(const float4*)&As[k][ty * TM];
            float4 b0 = *(const float4*)&Bs[k][tx * TN];
            float4 b1 = *(const float4*)&Bs[k][tx * TN + 4];
            float am[TM] = {a.x, a.y, a.z, a.w};
            float bn_[TN] = {b0.x, b0.y, b0.z, b0.w, b1.x, b1.y, b1.z, b1.w};
#pragma unroll
            for (int i = 0; i < TM; ++i)
#pragma unroll
                for (int j = 0; j < TN; ++j)
                    acc[i][j] += am[i] * bn_[j];
        }
        __syncthreads();
    }

    // write h as fp16 (8 halves = 16B per row-chunk)
#pragma unroll
    for (int i = 0; i < TM; ++i) {
        int row = bm + ty * TM + i;
        if (row < M) {
            __half2 h0 = __floats2half2_rn(acc[i][0], acc[i][1]);
            __half2 h1 = __floats2half2_rn(acc[i][2], acc[i][3]);
            __half2 h2 = __floats2half2_rn(acc[i][4], acc[i][5]);
            __half2 h3 = __floats2half2_rn(acc[i][6], acc[i][7]);
            uint4 u;
            u.x = *(uint32_t*)&h0; u.y = *(uint32_t*)&h1;
            u.z = *(uint32_t*)&h2; u.w = *(uint32_t*)&h3;
            *(uint4*)(g_h + (size_t)row * DOUT + bn + tx * TN) = u;
        }
    }
}

// ---------------- CSR build ----------------
__global__ void zero_count_kernel() {
    int i = blockIdx.x * blockDim.x + threadIdx.x;
    if (i < NNODES) g_count[i] = 0;
}

__global__ void hist_kernel(const int* __restrict__ edst, int E) {
    int e = blockIdx.x * blockDim.x + threadIdx.x;
    if (e < E) atomicAdd(&g_count[edst[e]], 1);
}

// scan pass A: per-block (1024-elem) sums
__global__ __launch_bounds__(1024) void scanA_kernel() {
    __shared__ int wsum[32];
    const int t = threadIdx.x, b = blockIdx.x;
    const int lane = t & 31, wid = t >> 5;
    int i = b * 1024 + t;
    int v = (i < NNODES) ? g_count[i] : 0;
    int s = v;
#pragma unroll
    for (int off = 16; off > 0; off >>= 1)
        s += __shfl_down_sync(0xffffffffu, s, off);
    if (lane == 0) wsum[wid] = s;
    __syncthreads();
    if (wid == 0) {
        int r = wsum[lane];
#pragma unroll
        for (int off = 16; off > 0; off >>= 1)
            r += __shfl_down_sync(0xffffffffu, r, off);
        if (lane == 0) g_bsum[b] = r;
    }
}

// scan pass B: exclusive scan of SCAN_BLK partials (single block, 128 thr)
__global__ __launch_bounds__(128) void scanB_kernel() {
    __shared__ int sh[128];
    const int t = threadIdx.x;
    int v = (t < SCAN_BLK) ? g_bsum[t] : 0;
    sh[t] = v;
    __syncthreads();
#pragma unroll
    for (int off = 1; off < 128; off <<= 1) {
        int y = (t >= off) ? sh[t - off] : 0;
        __syncthreads();
        sh[t] += y;
        __syncthreads();
    }
    if (t < SCAN_BLK) g_bpre[t] = sh[t] - v;       // exclusive
    if (t == 127) g_off[NNODES] = sh[127];         // grand total
}

// scan pass C: per-block exclusive scan + block prefix -> offsets/cursors
__global__ __launch_bounds__(1024) void scanC_kernel() {
    __shared__ int wsum[32];
    const int t = threadIdx.x, b = blockIdx.x;
    const int lane = t & 31, wid = t >> 5;
    int i = b * 1024 + t;
    int v = (i < NNODES) ? g_count[i] : 0;
    int x = v;
#pragma unroll
    for (int off = 1; off < 32; off <<= 1) {
        int y = __shfl_up_sync(0xffffffffu, x, off);
        if (lane >= off) x += y;
    }
    if (lane == 31) wsum[wid] = x;                 // warp totals
    __syncthreads();
    if (wid == 0) {
        int s0 = wsum[lane];
        int s = s0;
#pragma unroll
        for (int off = 1; off < 32; off <<= 1) {
            int y = __shfl_up_sync(0xffffffffu, s, off);
            if (lane >= off) s += y;
        }
        wsum[lane] = s - s0;                       // exclusive warp prefix
    }
    __syncthreads();
    if (i < NNODES) {
        int excl = (x - v) + wsum[wid] + g_bpre[b];
        g_off[i]    = excl;
        g_cursor[i] = excl;
    }
}

__global__ void reorder_kernel(const int* __restrict__ esrc,
                               const int* __restrict__ edst,
                               const float* __restrict__ ew, int E)
{
    int e = blockIdx.x * blockDim.x + threadIdx.x;
    if (e < E) {
        int d = edst[e];
        int pos = atomicAdd(&g_cursor[d], 1);
        g_edge_s[pos] = make_int2(esrc[e], __float_as_int(ew[e]));
    }
}

// ---------------- aggregation: 1 warp per dst node, fp16 gather ------------
__global__ __launch_bounds__(256) void agg_kernel(float* __restrict__ out, int N)
{
    int node = blockIdx.x * 8 + (threadIdx.x >> 5);
    int lane = threadIdx.x & 31;
    if (node >= N) return;

    int beg = g_off[node];
    int end = g_off[node + 1];

    float a[8] = {0.f, 0.f, 0.f, 0.f, 0.f, 0.f, 0.f, 0.f};

    for (int j = beg; j < end; j += 32) {
        int n = min(32, end - j);
        int2 e = (lane < n) ? __ldg(&g_edge_s[j + lane]) : make_int2(0, 0);
        for (int t = 0; t < n; ++t) {
            int   s = __shfl_sync(0xffffffffu, e.x, t);
            float w = __int_as_float(__shfl_sync(0xffffffffu, e.y, t));
            const uint4* hp = (const uint4*)(g_h + (size_t)s * DOUT);
            uint4 u = __ldg(hp + lane);            // 8 halves: cols lane*8..+7
            float2 f0 = __half22float2(*(__half2*)&u.x);
            float2 f1 = __half22float2(*(__half2*)&u.y);
            float2 f2 = __half22float2(*(__half2*)&u.z);
            float2 f3 = __half22float2(*(__half2*)&u.w);
            a[0] = fmaf(w, f0.x, a[0]); a[1] = fmaf(w, f0.y, a[1]);
            a[2] = fmaf(w, f1.x, a[2]); a[3] = fmaf(w, f1.y, a[3]);
            a[4] = fmaf(w, f2.x, a[4]); a[5] = fmaf(w, f2.y, a[5]);
            a[6] = fmaf(w, f3.x, a[6]); a[7] = fmaf(w, f3.y, a[7]);
        }
    }

#pragma unroll
    for (int i = 0; i < 8; ++i) a[i] = fmaxf(a[i], 0.f);

    float* op = out + (size_t)node * DOUT + lane * 8;
    *(float4*)(op)     = make_float4(a[0], a[1], a[2], a[3]);
    *(float4*)(op + 4) = make_float4(a[4], a[5], a[6], a[7]);
}

// ---------------- launch ----------------
extern "C" void kernel_launch(void* const* d_in, const int* in_sizes, int n_in,
                              void* d_out, int out_size)
{
    const float* x    = (const float*)d_in[0];
    const float* W    = (const float*)d_in[1];
    const int*   esrc = (const int*)d_in[2];
    const int*   edst = (const int*)d_in[3];
    const float* ew   = (const float*)d_in[4];
    float*       out  = (float*)d_out;

    const int M = in_sizes[0] / DIN;   // 100000
    const int E = in_sizes[2];         // 3200000

    // 1) h = dropout(x) @ W   (fp16 h)
    dim3 gblk(DOUT / BN, (M + BM - 1) / BM);
    gemm_dropout_kernel<<<gblk, dim3(16, 16)>>>(x, W, M);

    // 2) CSR build (dst-major edge ordering)
    zero_count_kernel<<<(NNODES + 255) / 256, 256>>>();
    hist_kernel<<<(E + 255) / 256, 256>>>(edst, E);
    scanA_kernel<<<SCAN_BLK, 1024>>>();
    scanB_kernel<<<1, 128>>>();
    scanC_kernel<<<SCAN_BLK, 1024>>>();
    reorder_kernel<<<(E + 255) / 256, 256>>>(esrc, edst, ew, E);

    // 3) aggregate + relu, one warp per dst node, plain stores
    agg_kernel<<<(M + 7) / 8, 256>>>(out, M);
}

// round 7
// speedup vs baseline: 2.0259x; 1.2684x over previous
#include <cuda_runtime.h>
#include <cuda_fp16.h>
#include <cuda_bf16.h>
#include <mma.h>
#include <cstdint>

using namespace nvcuda;

// ---------------- problem constants ----------------
#define NNODES   100000
#define DIN      512
#define DOUT     256
#define EDGES_MAX 3200000
#define KEEP_THRESH 7549747u          // 0.9f == 7549747 * 2^-23 exactly
#define INV_KEEP (1.0f/0.9f)
#define SCAN_BLK  98

// GEMM tiling (wmma, legacy HMMA path — compute_103-safe)
#define BMT 128
#define BNT 128
#define KC  32
#define NCHUNK (DIN / KC)             // 16
#define LDS_T 40                      // smem row stride (elems), 80B = mult of 16B

// scratch
__device__ __half         g_h[(size_t)NNODES * DOUT];   // 51.2 MB fp16
__device__ __nv_bfloat16  g_Bhi[DOUT * DIN];            // W split, K-major [n][k]
__device__ __nv_bfloat16  g_Blo[DOUT * DIN];
__device__ int            g_count[NNODES];
__device__ int            g_off[NNODES + 1];
__device__ int            g_cursor[NNODES];
__device__ int            g_bsum[SCAN_BLK];
__device__ int            g_bpre[SCAN_BLK];
__device__ int2           g_edge_s[EDGES_MAX];

// ---------------- JAX threefry2x32, partitionable layout (key = (0,42)) ----
__device__ __forceinline__ uint32_t rotl32(uint32_t x, int r) {
    return __funnelshift_l(x, x, r);
}

__device__ __forceinline__ uint32_t threefry_bits(uint32_t idx) {
    const uint32_t ks0 = 0u;
    const uint32_t ks1 = 42u;
    const uint32_t ks2 = 0x1BD11BDAu ^ 42u;
    uint32_t x0 = 0u;
    uint32_t x1 = idx;
    x0 += ks0; x1 += ks1;
#define TFR(r) { x0 += x1; x1 = rotl32(x1, r); x1 ^= x0; }
    TFR(13) TFR(15) TFR(26) TFR(6)   x0 += ks1; x1 += ks2 + 1u;
    TFR(17) TFR(29) TFR(16) TFR(24)  x0 += ks2; x1 += ks0 + 2u;
    TFR(13) TFR(15) TFR(26) TFR(6)   x0 += ks0; x1 += ks1 + 3u;
    TFR(17) TFR(29) TFR(16) TFR(24)  x0 += ks1; x1 += ks2 + 4u;
    TFR(13) TFR(15) TFR(26) TFR(6)   x0 += ks2; x1 += ks0 + 5u;
#undef TFR
    return x0 ^ x1;
}

__device__ __forceinline__ float dropout_val(float v, uint32_t idx) {
    uint32_t m = threefry_bits(idx) >> 9;
    return (m < KEEP_THRESH) ? v * INV_KEEP : 0.0f;
}

// ---------------- kernel 0: split W into bf16 hi/lo, K-major [n][k] --------
__global__ void wsplit_kernel(const float* __restrict__ W) {
    int i = blockIdx.x * blockDim.x + threadIdx.x;
    if (i < DOUT * DIN) {
        int n = i >> 9;           // /DIN
        int k = i & (DIN - 1);
        float w = W[(size_t)k * DOUT + n];
        __nv_bfloat16 hi = __float2bfloat16(w);
        float lo = w - __bfloat162float(hi);
        g_Bhi[i] = hi;
        g_Blo[i] = __float2bfloat16(lo);
    }
}

// ---------------- kernel 1: dropout + split-bf16 wmma GEMM -----------------
// CTA tile 128x128; 8 warps in 4(M) x 2(N); warp tile 32x64 = 2x4 frags.
// C = Ah*Bh + Ah*Bl + Al*Bh  (fp32 accum), h stored fp16.
__global__ void __launch_bounds__(256) gemm_wmma_kernel(
    const float* __restrict__ x, int M)
{
    __shared__ __nv_bfloat16 Ahi[BMT][LDS_T];
    __shared__ __nv_bfloat16 Alo[BMT][LDS_T];
    __shared__ __nv_bfloat16 Bhi[BNT][LDS_T];   // [n][k]
    __shared__ __nv_bfloat16 Blo[BNT][LDS_T];

    const int tid  = threadIdx.x;
    const int wid  = tid >> 5;
    const int lane = tid & 31;
    const int wm = wid & 3;              // 0..3 -> M offset wm*32
    const int wn = wid >> 2;             // 0..1 -> N offset wn*64
    const int bm = blockIdx.y * BMT;
    const int bn = blockIdx.x * BNT;

    // A-prep map: 2 threads per row, 16 k each
    const int arow = tid >> 1;                 // 0..127
    const int akof = (tid & 1) * 16;           // 0 / 16
    const int grow = bm + arow;
    const bool rok = (grow < M);

    // B-load map: 2 threads per n-row, 16 k each (2 x uint4)
    const int brow = tid >> 1;
    const int bkof = (tid & 1) * 16;

    wmma::fragment<wmma::accumulator, 16, 16, 16, float> c[2][4];
#pragma unroll
    for (int i = 0; i < 2; ++i)
#pragma unroll
        for (int j = 0; j < 4; ++j) wmma::fill_fragment(c[i][j], 0.0f);

    for (int ch = 0; ch < NCHUNK; ++ch) {
        const int k0 = ch * KC;

        // ---- A: dropout + hi/lo split ----
        {
            float f[16];
            if (rok) {
#pragma unroll
                for (int q = 0; q < 4; ++q) {
                    float4 v = *(const float4*)(x + (size_t)grow * DIN + k0 + akof + q * 4);
                    uint32_t base = (uint32_t)grow * DIN + (uint32_t)(k0 + akof + q * 4);
                    f[q*4+0] = dropout_val(v.x, base);
                    f[q*4+1] = dropout_val(v.y, base + 1u);
                    f[q*4+2] = dropout_val(v.z, base + 2u);
                    f[q*4+3] = dropout_val(v.w, base + 3u);
                }
            } else {
#pragma unroll
                for (int q = 0; q < 16; ++q) f[q] = 0.f;
            }
#pragma unroll
            for (int q = 0; q < 16; ++q) {
                __nv_bfloat16 hi = __float2bfloat16(f[q]);
                Ahi[arow][akof + q] = hi;
                Alo[arow][akof + q] = __float2bfloat16(f[q] - __bfloat162float(hi));
            }
        }

        // ---- B: load pre-split planes ----
        {
            const __nv_bfloat16* ph = g_Bhi + (size_t)(bn + brow) * DIN + k0 + bkof;
            const __nv_bfloat16* pl = g_Blo + (size_t)(bn + brow) * DIN + k0 + bkof;
            uint4 h0 = *(const uint4*)(ph);
            uint4 h1 = *(const uint4*)(ph + 8);
            uint4 l0 = *(const uint4*)(pl);
            uint4 l1 = *(const uint4*)(pl + 8);
            *(uint4*)&Bhi[brow][bkof]     = h0;
            *(uint4*)&Bhi[brow][bkof + 8] = h1;
            *(uint4*)&Blo[brow][bkof]     = l0;
            *(uint4*)&Blo[brow][bkof + 8] = l1;
        }
        __syncthreads();

        // ---- MMA: 2 ksteps x (2x4 tiles) x 3 products ----
#pragma unroll
        for (int ks = 0; ks < 2; ++ks) {
            wmma::fragment<wmma::matrix_a, 16, 16, 16, __nv_bfloat16, wmma::row_major> ah[2], al[2];
            wmma::fragment<wmma::matrix_b, 16, 16, 16, __nv_bfloat16, wmma::col_major> bh[4], bl[4];
#pragma unroll
            for (int i = 0; i < 2; ++i) {
                wmma::load_matrix_sync(ah[i], &Ahi[wm*32 + i*16][ks*16], LDS_T);
                wmma::load_matrix_sync(al[i], &Alo[wm*32 + i*16][ks*16], LDS_T);
            }
#pragma unroll
            for (int j = 0; j < 4; ++j) {
                wmma::load_matrix_sync(bh[j], &Bhi[wn*64 + j*16][ks*16], LDS_T);
                wmma::load_matrix_sync(bl[j], &Blo[wn*64 + j*16][ks*16], LDS_T);
            }
#pragma unroll
            for (int i = 0; i < 2; ++i)
#pragma unroll
                for (int j = 0; j < 4; ++j) {
                    wmma::mma_sync(c[i][j], ah[i], bh[j], c[i][j]);
                    wmma::mma_sync(c[i][j], ah[i], bl[j], c[i][j]);
                    wmma::mma_sync(c[i][j], al[i], bh[j], c[i][j]);
                }
        }
        __syncthreads();
    }

    // ---- epilogue: per-warp 16x16 patch -> fp16 g_h ----
    // reuse Ahi region as fp32 patches: warp w owns floats [w*256 .. w*256+255]
    float* patch = (float*)&Ahi[0][0] + wid * 256;
    const int prow = lane >> 1;                 // 0..15
    const int pcol = (lane & 1) * 8;            // 0 / 8

#pragma unroll
    for (int i = 0; i < 2; ++i)
#pragma unroll
        for (int j = 0; j < 4; ++j) {
            wmma::store_matrix_sync(patch, c[i][j], 16, wmma::mem_row_major);
            __syncwarp();
            int orow = bm + wm*32 + i*16 + prow;
            if (orow < M) {
                const float* pr = patch + prow * 16 + pcol;
                __half2 p0 = __floats2half2_rn(pr[0], pr[1]);
                __half2 p1 = __floats2half2_rn(pr[2], pr[3]);
                __half2 p2 = __floats2half2_rn(pr[4], pr[5]);
                __half2 p3 = __floats2half2_rn(pr[6], pr[7]);
                uint4 u;
                u.x = *(uint32_t*)&p0; u.y = *(uint32_t*)&p1;
                u.z = *(uint32_t*)&p2; u.w = *(uint32_t*)&p3;
                *(uint4*)(g_h + (size_t)orow * DOUT + bn + wn*64 + j*16 + pcol) = u;
            }
            __syncwarp();
        }
}

// ---------------- CSR build ----------------
__global__ void zero_count_kernel() {
    int i = blockIdx.x * blockDim.x + threadIdx.x;
    if (i < NNODES) g_count[i] = 0;
}

__global__ void hist_kernel(const int* __restrict__ edst, int E) {
    int e = blockIdx.x * blockDim.x + threadIdx.x;
    if (e < E) atomicAdd(&g_count[edst[e]], 1);
}

__global__ __launch_bounds__(1024) void scanA_kernel() {
    __shared__ int wsum[32];
    const int t = threadIdx.x, b = blockIdx.x;
    const int lane = t & 31, wid = t >> 5;
    int i = b * 1024 + t;
    int v = (i < NNODES) ? g_count[i] : 0;
    int s = v;
#pragma unroll
    for (int off = 16; off > 0; off >>= 1)
        s += __shfl_down_sync(0xffffffffu, s, off);
    if (lane == 0) wsum[wid] = s;
    __syncthreads();
    if (wid == 0) {
        int r = wsum[lane];
#pragma unroll
        for (int off = 16; off > 0; off >>= 1)
            r += __shfl_down_sync(0xffffffffu, r, off);
        if (lane == 0) g_bsum[b] = r;
    }
}

__global__ __launch_bounds__(128) void scanB_kernel() {
    __shared__ int sh[128];
    const int t = threadIdx.x;
    int v = (t < SCAN_BLK) ? g_bsum[t] : 0;
    sh[t] = v;
    __syncthreads();
#pragma unroll
    for (int off = 1; off < 128; off <<= 1) {
        int y = (t >= off) ? sh[t - off] : 0;
        __syncthreads();
        sh[t] += y;
        __syncthreads();
    }
    if (t < SCAN_BLK) g_bpre[t] = sh[t] - v;
    if (t == 127) g_off[NNODES] = sh[127];
}

__global__ __launch_bounds__(1024) void scanC_kernel() {
    __shared__ int wsum[32];
    const int t = threadIdx.x, b = blockIdx.x;
    const int lane = t & 31, wid = t >> 5;
    int i = b * 1024 + t;
    int v = (i < NNODES) ? g_count[i] : 0;
    int xv = v;
#pragma unroll
    for (int off = 1; off < 32; off <<= 1) {
        int y = __shfl_up_sync(0xffffffffu, xv, off);
        if (lane >= off) xv += y;
    }
    if (lane == 31) wsum[wid] = xv;
    __syncthreads();
    if (wid == 0) {
        int s0 = wsum[lane];
        int s = s0;
#pragma unroll
        for (int off = 1; off < 32; off <<= 1) {
            int y = __shfl_up_sync(0xffffffffu, s, off);
            if (lane >= off) s += y;
        }
        wsum[lane] = s - s0;
    }
    __syncthreads();
    if (i < NNODES) {
        int excl = (xv - v) + wsum[wid] + g_bpre[b];
        g_off[i]    = excl;
        g_cursor[i] = excl;
    }
}

__global__ void reorder_kernel(const int* __restrict__ esrc,
                               const int* __restrict__ edst,
                               const float* __restrict__ ew, int E)
{
    int e = blockIdx.x * blockDim.x + threadIdx.x;
    if (e < E) {
        int d = edst[e];
        int pos = atomicAdd(&g_cursor[d], 1);
        g_edge_s[pos] = make_int2(esrc[e], __float_as_int(ew[e]));
    }
}

// ---------------- aggregation: 1 warp per dst node, fp16 gather ------------
__global__ __launch_bounds__(256) void agg_kernel(float* __restrict__ out, int N)
{
    int node = blockIdx.x * 8 + (threadIdx.x >> 5);
    int lane = threadIdx.x & 31;
    if (node >= N) return;

    int beg = g_off[node];
    int end = g_off[node + 1];

    float a[8] = {0.f, 0.f, 0.f, 0.f, 0.f, 0.f, 0.f, 0.f};

    for (int j = beg; j < end; j += 32) {
        int n = min(32, end - j);
        int2 e = (lane < n) ? __ldg(&g_edge_s[j + lane]) : make_int2(0, 0);
        for (int t = 0; t < n; ++t) {
            int   s = __shfl_sync(0xffffffffu, e.x, t);
            float w = __int_as_float(__shfl_sync(0xffffffffu, e.y, t));
            const uint4* hp = (const uint4*)(g_h + (size_t)s * DOUT);
            uint4 u = __ldg(hp + lane);
            float2 f0 = __half22float2(*(__half2*)&u.x);
            float2 f1 = __half22float2(*(__half2*)&u.y);
            float2 f2 = __half22float2(*(__half2*)&u.z);
            float2 f3 = __half22float2(*(__half2*)&u.w);
            a[0] = fmaf(w, f0.x, a[0]); a[1] = fmaf(w, f0.y, a[1]);
            a[2] = fmaf(w, f1.x, a[2]); a[3] = fmaf(w, f1.y, a[3]);
            a[4] = fmaf(w, f2.x, a[4]); a[5] = fmaf(w, f2.y, a[5]);
            a[6] = fmaf(w, f3.x, a[6]); a[7] = fmaf(w, f3.y, a[7]);
        }
    }

#pragma unroll
    for (int i = 0; i < 8; ++i) a[i] = fmaxf(a[i], 0.f);

    float* op = out + (size_t)node * DOUT + lane * 8;
    *(float4*)(op)     = make_float4(a[0], a[1], a[2], a[3]);
    *(float4*)(op + 4) = make_float4(a[4], a[5], a[6], a[7]);
}

// ---------------- launch ----------------
extern "C" void kernel_launch(void* const* d_in, const int* in_sizes, int n_in,
                              void* d_out, int out_size)
{
    const float* x    = (const float*)d_in[0];
    const float* W    = (const float*)d_in[1];
    const int*   esrc = (const int*)d_in[2];
    const int*   edst = (const int*)d_in[3];
    const float* ew   = (const float*)d_in[4];
    float*       out  = (float*)d_out;

    const int M = in_sizes[0] / DIN;   // 100000
    const int E = in_sizes[2];         // 3200000

    // 1) W split + wmma tensor-core GEMM (h in fp16)
    wsplit_kernel<<<(DOUT * DIN + 255) / 256, 256>>>(W);
    dim3 gg(DOUT / BNT, (M + BMT - 1) / BMT);
    gemm_wmma_kernel<<<gg, 256>>>(x, M);

    // 2) CSR build (dst-major edge ordering)
    zero_count_kernel<<<(NNODES + 255) / 256, 256>>>();
    hist_kernel<<<(E + 255) / 256, 256>>>(edst, E);
    scanA_kernel<<<SCAN_BLK, 1024>>>();
    scanB_kernel<<<1, 128>>>();
    scanC_kernel<<<SCAN_BLK, 1024>>>();
    reorder_kernel<<<(E + 255) / 256, 256>>>(esrc, edst, ew, E);

    // 3) aggregate + relu, one warp per dst node, plain stores
    agg_kernel<<<(M + 7) / 8, 256>>>(out, M);
}

// round 10
// speedup vs baseline: 2.2150x; 1.0934x over previous
#include <cuda_runtime.h>
#include <cuda_fp16.h>
#include <cuda_bf16.h>
#include <mma.h>
#include <cstdint>

using namespace nvcuda;

// ---------------- problem constants ----------------
#define NNODES   100000
#define DIN      512
#define DOUT     256
#define EDGES_MAX 3200000
#define KEEP_THRESH 7549747u          // 0.9f == 7549747 * 2^-23 exactly
#define INV_KEEP (1.0f/0.9f)
#define SCAN_BLK  98

// GEMM tiling (wmma HMMA path, compute_103-safe)
#define BMT 64
#define BNT 256
#define KC  32
#define NCHUNK (DIN / KC)             // 16
#define LDS_T 36                      // smem row stride elems (72B; 8B-aligned rows,
                                      // frag-load ptrs use 16-row multiples -> 32B aligned)

// scratch
__device__ __half         g_h[(size_t)NNODES * DOUT];   // 51.2 MB fp16
__device__ __nv_bfloat16  g_Bhi[DOUT * DIN];            // W split, K-major [n][k]
__device__ __nv_bfloat16  g_Blo[DOUT * DIN];
__device__ int            g_count[NNODES];
__device__ int            g_off[NNODES + 1];
__device__ int            g_cursor[NNODES];
__device__ int            g_bsum[SCAN_BLK];
__device__ int            g_bpre[SCAN_BLK];
__device__ int2           g_edge_s[EDGES_MAX];

// ---------------- JAX threefry2x32, partitionable layout (key = (0,42)) ----
__device__ __forceinline__ uint32_t rotl32(uint32_t x, int r) {
    return __funnelshift_l(x, x, r);
}

__device__ __forceinline__ uint32_t threefry_bits(uint32_t idx) {
    const uint32_t ks0 = 0u;
    const uint32_t ks1 = 42u;
    const uint32_t ks2 = 0x1BD11BDAu ^ 42u;
    uint32_t x0 = 0u;
    uint32_t x1 = idx;
    x0 += ks0; x1 += ks1;
#define TFR(r) { x0 += x1; x1 = rotl32(x1, r); x1 ^= x0; }
    TFR(13) TFR(15) TFR(26) TFR(6)   x0 += ks1; x1 += ks2 + 1u;
    TFR(17) TFR(29) TFR(16) TFR(24)  x0 += ks2; x1 += ks0 + 2u;
    TFR(13) TFR(15) TFR(26) TFR(6)   x0 += ks0; x1 += ks1 + 3u;
    TFR(17) TFR(29) TFR(16) TFR(24)  x0 += ks1; x1 += ks2 + 4u;
    TFR(13) TFR(15) TFR(26) TFR(6)   x0 += ks2; x1 += ks0 + 5u;
#undef TFR
    return x0 ^ x1;
}

__device__ __forceinline__ float dropout_val(float v, uint32_t idx) {
    uint32_t m = threefry_bits(idx) >> 9;
    return (m < KEEP_THRESH) ? v * INV_KEEP : 0.0f;
}

// ---------------- kernel 0: split W into bf16 hi/lo, K-major [n][k] --------
__global__ void wsplit_kernel(const float* __restrict__ W) {
    int i = blockIdx.x * blockDim.x + threadIdx.x;
    if (i < DOUT * DIN) {
        int n = i >> 9;           // /DIN
        int k = i & (DIN - 1);
        float w = W[(size_t)k * DOUT + n];
        __nv_bfloat16 hi = __float2bfloat16(w);
        float lo = w - __bfloat162float(hi);
        g_Bhi[i] = hi;
        g_Blo[i] = __float2bfloat16(lo);
    }
}

// ---------------- kernel 1: dropout + split-bf16 wmma GEMM -----------------
// CTA tile 64x256 (full DOUT): threefry computed exactly once per x element.
// 8 warps in 2(M) x 4(N); warp tile 32x64 = 2x4 frags.
// C = Ah*Bh + Ah*Bl + Al*Bh  (fp32 accum), h stored fp16.
__global__ void __launch_bounds__(256) gemm_wmma_kernel(
    const float* __restrict__ x, int M)
{
    __shared__ __align__(32) __nv_bfloat16 Ahi[BMT][LDS_T];
    __shared__ __align__(32) __nv_bfloat16 Alo[BMT][LDS_T];
    __shared__ __align__(32) __nv_bfloat16 Bhi[BNT][LDS_T];   // [n][k]
    __shared__ __align__(32) __nv_bfloat16 Blo[BNT][LDS_T];

    const int tid  = threadIdx.x;
    const int wid  = tid >> 5;
    const int lane = tid & 31;
    const int wm = wid & 1;              // 0..1 -> M offset wm*32
    const int wn = wid >> 1;             // 0..3 -> N offset wn*64
    const int bm = blockIdx.x * BMT;

    // A-prep map: 4 threads per row, 8 k each
    const int arow = tid >> 2;                 // 0..63
    const int akof = (tid & 3) * 8;            // 0,8,16,24
    const int grow = bm + arow;
    const bool rok = (grow < M);

    wmma::fragment<wmma::accumulator, 16, 16, 16, float> c[2][4];
#pragma unroll
    for (int i = 0; i < 2; ++i)
#pragma unroll
        for (int j = 0; j < 4; ++j) wmma::fill_fragment(c[i][j], 0.0f);

    for (int ch = 0; ch < NCHUNK; ++ch) {
        const int k0 = ch * KC;

        // ---- A: dropout + hi/lo split (once per element, 8 per thread) ----
        {
            float f[8];
            if (rok) {
#pragma unroll
                for (int q = 0; q < 2; ++q) {
                    float4 v = *(const float4*)(x + (size_t)grow * DIN + k0 + akof + q * 4);
                    uint32_t base = (uint32_t)grow * DIN + (uint32_t)(k0 + akof + q * 4);
                    f[q*4+0] = dropout_val(v.x, base);
                    f[q*4+1] = dropout_val(v.y, base + 1u);
                    f[q*4+2] = dropout_val(v.z, base + 2u);
                    f[q*4+3] = dropout_val(v.w, base + 3u);
                }
            } else {
#pragma unroll
                for (int q = 0; q < 8; ++q) f[q] = 0.f;
            }
#pragma unroll
            for (int q = 0; q < 8; ++q) {
                __nv_bfloat16 hi = __float2bfloat16(f[q]);
                Ahi[arow][akof + q] = hi;
                Alo[arow][akof + q] = __float2bfloat16(f[q] - __bfloat162float(hi));
            }
        }

        // ---- B: load pre-split planes (L2-resident, 256KB total) ----
        // 8-byte smem stores only: row stride 72B is 8B-aligned for every row.
        {
            const __nv_bfloat16* ph = g_Bhi + (size_t)tid * DIN + k0;
            const __nv_bfloat16* pl = g_Blo + (size_t)tid * DIN + k0;
#pragma unroll
            for (int q = 0; q < 4; ++q) {
                uint4 vh = __ldg((const uint4*)(ph) + q);
                uint4 vl = __ldg((const uint4*)(pl) + q);
                *(uint2*)&Bhi[tid][q * 8]     = make_uint2(vh.x, vh.y);
                *(uint2*)&Bhi[tid][q * 8 + 4] = make_uint2(vh.z, vh.w);
                *(uint2*)&Blo[tid][q * 8]     = make_uint2(vl.x, vl.y);
                *(uint2*)&Blo[tid][q * 8 + 4] = make_uint2(vl.z, vl.w);
            }
        }
        __syncthreads();

        // ---- MMA: 2 ksteps x (2x4 tiles) x 3 products ----
#pragma unroll
        for (int ks = 0; ks < 2; ++ks) {
            wmma::fragment<wmma::matrix_a, 16, 16, 16, __nv_bfloat16, wmma::row_major> ah[2], al[2];
            wmma::fragment<wmma::matrix_b, 16, 16, 16, __nv_bfloat16, wmma::col_major> bh[4], bl[4];
#pragma unroll
            for (int i = 0; i < 2; ++i) {
                wmma::load_matrix_sync(ah[i], &Ahi[wm*32 + i*16][ks*16], LDS_T);
                wmma::load_matrix_sync(al[i], &Alo[wm*32 + i*16][ks*16], LDS_T);
            }
#pragma unroll
            for (int j = 0; j < 4; ++j) {
                wmma::load_matrix_sync(bh[j], &Bhi[wn*64 + j*16][ks*16], LDS_T);
                wmma::load_matrix_sync(bl[j], &Blo[wn*64 + j*16][ks*16], LDS_T);
            }
#pragma unroll
            for (int i = 0; i < 2; ++i)
#pragma unroll
                for (int j = 0; j < 4; ++j) {
                    wmma::mma_sync(c[i][j], ah[i], bh[j], c[i][j]);
                    wmma::mma_sync(c[i][j], ah[i], bl[j], c[i][j]);
                    wmma::mma_sync(c[i][j], al[i], bh[j], c[i][j]);
                }
        }
        __syncthreads();
    }

    // ---- epilogue: per-warp 16x16 patch (in Bhi region) -> fp16 g_h ----
    float* patch = (float*)&Bhi[0][0] + wid * 256;
    const int prow = lane >> 1;                 // 0..15
    const int pcol = (lane & 1) * 8;            // 0 / 8

#pragma unroll
    for (int i = 0; i < 2; ++i)
#pragma unroll
        for (int j = 0; j < 4; ++j) {
            wmma::store_matrix_sync(patch, c[i][j], 16, wmma::mem_row_major);
            __syncwarp();
            int orow = bm + wm*32 + i*16 + prow;
            if (orow < M) {
                const float* pr = patch + prow * 16 + pcol;
                __half2 p0 = __floats2half2_rn(pr[0], pr[1]);
                __half2 p1 = __floats2half2_rn(pr[2], pr[3]);
                __half2 p2 = __floats2half2_rn(pr[4], pr[5]);
                __half2 p3 = __floats2half2_rn(pr[6], pr[7]);
                uint4 u;
                u.x = *(uint32_t*)&p0; u.y = *(uint32_t*)&p1;
                u.z = *(uint32_t*)&p2; u.w = *(uint32_t*)&p3;
                *(uint4*)(g_h + (size_t)orow * DOUT + wn*64 + j*16 + pcol) = u;
            }
            __syncwarp();
        }
}

// ---------------- CSR build ----------------
__global__ void zero_count_kernel() {
    int i = blockIdx.x * blockDim.x + threadIdx.x;
    if (i < NNODES) g_count[i] = 0;
}

__global__ void hist_kernel(const int* __restrict__ edst, int E) {
    int e = blockIdx.x * blockDim.x + threadIdx.x;
    if (e < E) atomicAdd(&g_count[edst[e]], 1);
}

__global__ __launch_bounds__(1024) void scanA_kernel() {
    __shared__ int wsum[32];
    const int t = threadIdx.x, b = blockIdx.x;
    const int lane = t & 31, wid = t >> 5;
    int i = b * 1024 + t;
    int v = (i < NNODES) ? g_count[i] : 0;
    int s = v;
#pragma unroll
    for (int off = 16; off > 0; off >>= 1)
        s += __shfl_down_sync(0xffffffffu, s, off);
    if (lane == 0) wsum[wid] = s;
    __syncthreads();
    if (wid == 0) {
        int r = wsum[lane];
#pragma unroll
        for (int off = 16; off > 0; off >>= 1)
            r += __shfl_down_sync(0xffffffffu, r, off);
        if (lane == 0) g_bsum[b] = r;
    }
}

__global__ __launch_bounds__(128) void scanB_kernel() {
    __shared__ int sh[128];
    const int t = threadIdx.x;
    int v = (t < SCAN_BLK) ? g_bsum[t] : 0;
    sh[t] = v;
    __syncthreads();
#pragma unroll
    for (int off = 1; off < 128; off <<= 1) {
        int y = (t >= off) ? sh[t - off] : 0;
        __syncthreads();
        sh[t] += y;
        __syncthreads();
    }
    if (t < SCAN_BLK) g_bpre[t] = sh[t] - v;
    if (t == 127) g_off[NNODES] = sh[127];
}

__global__ __launch_bounds__(1024) void scanC_kernel() {
    __shared__ int wsum[32];
    const int t = threadIdx.x, b = blockIdx.x;
    const int lane = t & 31, wid = t >> 5;
    int i = b * 1024 + t;
    int v = (i < NNODES) ? g_count[i] : 0;
    int xv = v;
#pragma unroll
    for (int off = 1; off < 32; off <<= 1) {
        int y = __shfl_up_sync(0xffffffffu, xv, off);
        if (lane >= off) xv += y;
    }
    if (lane == 31) wsum[wid] = xv;
    __syncthreads();
    if (wid == 0) {
        int s0 = wsum[lane];
        int s = s0;
#pragma unroll
        for (int off = 1; off < 32; off <<= 1) {
            int y = __shfl_up_sync(0xffffffffu, s, off);
            if (lane >= off) s += y;
        }
        wsum[lane] = s - s0;
    }
    __syncthreads();
    if (i < NNODES) {
        int excl = (xv - v) + wsum[wid] + g_bpre[b];
        g_off[i]    = excl;
        g_cursor[i] = excl;
    }
}

__global__ void reorder_kernel(const int* __restrict__ esrc,
                               const int* __restrict__ edst,
                               const float* __restrict__ ew, int E)
{
    int e = blockIdx.x * blockDim.x + threadIdx.x;
    if (e < E) {
        int d = edst[e];
        int pos = atomicAdd(&g_cursor[d], 1);
        g_edge_s[pos] = make_int2(esrc[e], __float_as_int(ew[e]));
    }
}

// ---------------- aggregation: 1 warp per dst node, fp16 gather ------------
__global__ __launch_bounds__(256) void agg_kernel(float* __restrict__ out, int N)
{
    int node = blockIdx.x * 8 + (threadIdx.x >> 5);
    int lane = threadIdx.x & 31;
    if (node >= N) return;

    int beg = g_off[node];
    int end = g_off[node + 1];

    float a[8] = {0.f, 0.f, 0.f, 0.f, 0.f, 0.f, 0.f, 0.f};

    for (int j = beg; j < end; j += 32) {
        int n = min(32, end - j);
        int2 e = (lane < n) ? __ldg(&g_edge_s[j + lane]) : make_int2(0, 0);
        for (int t = 0; t < n; ++t) {
            int   s = __shfl_sync(0xffffffffu, e.x, t);
            float w = __int_as_float(__shfl_sync(0xffffffffu, e.y, t));
            const uint4* hp = (const uint4*)(g_h + (size_t)s * DOUT);
            uint4 u = __ldg(hp + lane);
            float2 f0 = __half22float2(*(__half2*)&u.x);
            float2 f1 = __half22float2(*(__half2*)&u.y);
            float2 f2 = __half22float2(*(__half2*)&u.z);
            float2 f3 = __half22float2(*(__half2*)&u.w);
            a[0] = fmaf(w, f0.x, a[0]); a[1] = fmaf(w, f0.y, a[1]);
            a[2] = fmaf(w, f1.x, a[2]); a[3] = fmaf(w, f1.y, a[3]);
            a[4] = fmaf(w, f2.x, a[4]); a[5] = fmaf(w, f2.y, a[5]);
            a[6] = fmaf(w, f3.x, a[6]); a[7] = fmaf(w, f3.y, a[7]);
        }
    }

#pragma unroll
    for (int i = 0; i < 8; ++i) a[i] = fmaxf(a[i], 0.f);

    float* op = out + (size_t)node * DOUT + lane * 8;
    *(float4*)(op)     = make_float4(a[0], a[1], a[2], a[3]);
    *(float4*)(op + 4) = make_float4(a[4], a[5], a[6], a[7]);
}

// ---------------- launch ----------------
extern "C" void kernel_launch(void* const* d_in, const int* in_sizes, int n_in,
                              void* d_out, int out_size)
{
    const float* x    = (const float*)d_in[0];
    const float* W    = (const float*)d_in[1];
    const int*   esrc = (const int*)d_in[2];
    const int*   edst = (const int*)d_in[3];
    const float* ew   = (const float*)d_in[4];
    float*       out  = (float*)d_out;

    const int M = in_sizes[0] / DIN;   // 100000
    const int E = in_sizes[2];         // 3200000

    // 1) W split + wmma tensor-core GEMM (h in fp16), threefry once per elem
    wsplit_kernel<<<(DOUT * DIN + 255) / 256, 256>>>(W);
    gemm_wmma_kernel<<<(M + BMT - 1) / BMT, 256>>>(x, M);

    // 2) CSR build (dst-major edge ordering)
    zero_count_kernel<<<(NNODES + 255) / 256, 256>>>();
    hist_kernel<<<(E + 255) / 256, 256>>>(edst, E);
    scanA_kernel<<<SCAN_BLK, 1024>>>();
    scanB_kernel<<<1, 128>>>();
    scanC_kernel<<<SCAN_BLK, 1024>>>();
    reorder_kernel<<<(E + 255) / 256, 256>>>(esrc, edst, ew, E);

    // 3) aggregate + relu, one warp per dst node, plain stores
    agg_kernel<<<(M + 7) / 8, 256>>>(out, M);
}